// round 12
// baseline (speedup 1.0000x reference)
#include <cuda_runtime.h>
#include <cstdint>
#include <math.h>

#define E_TOT 102400
#define NGRAPH 64
#define D_IN   1408
#define H1     512
#define H2     512
#define H3     256

// ---------------- scratch (__device__ globals; no allocs allowed) ----------
__device__ float g_Y1[(size_t)E_TOT * H1];   // also holds sigmoid output for LN
__device__ float g_Y2[(size_t)E_TOT * H2];
__device__ int   g_gcum[NGRAPH + 1];

// ---------------- helpers ---------------------------------------------------
#define CP_ASYNC16(dst, src) \
    asm volatile("cp.async.cg.shared.global [%0], [%1], 16;" :: "r"(dst), "l"(src) : "memory")
#define CP_COMMIT() asm volatile("cp.async.commit_group;" ::: "memory")
#define CP_WAIT(n)  asm volatile("cp.async.wait_group %0;" :: "n"(n) : "memory")

__device__ __forceinline__ uint32_t smem_u32(const void* p) {
    uint32_t a;
    asm("{ .reg .u64 t; cvta.to.shared.u64 t, %1; cvt.u32.u64 %0, t; }"
        : "=r"(a) : "l"(p));
    return a;
}

// m16n8k8 tf32 mma: D(16x8,f32) += A(16x8,tf32) * B(8x8,tf32)
__device__ __forceinline__ void mma_tf32(float* c, const uint32_t* a,
                                         uint32_t b0, uint32_t b1) {
    asm volatile(
        "mma.sync.aligned.m16n8k8.row.col.f32.tf32.tf32.f32 "
        "{%0,%1,%2,%3}, {%4,%5,%6,%7}, {%8,%9}, {%0,%1,%2,%3};"
        : "+f"(c[0]), "+f"(c[1]), "+f"(c[2]), "+f"(c[3])
        : "r"(a[0]), "r"(a[1]), "r"(a[2]), "r"(a[3]), "r"(b0), "r"(b1));
}

// ---------------- Kernel 0: prefix sum of num -------------------------------
__global__ void k_prefix(const int* __restrict__ num) {
    if (threadIdx.x == 0) {
        int s = 0;
        g_gcum[0] = 0;
        for (int i = 0; i < NGRAPH; i++) { s += num[i]; g_gcum[i + 1] = s; }
    }
}

// ---------------- tiled tf32 GEMM -------------------------------------------
// The proven R4 kernel; ONLY change: __launch_bounds__(256, 3) caps regs at 85
// so 3 CTAs/SM become resident (smem: 3 x 71680 = 215KB <= 228KB).
// Tile: BM=128, BN=128, BK=32. 256 threads = 8 warps (4M x 2N), warp 32x64.
// A smem: 128 rows x 36 words; B smem: 32 k-rows x 136 words. Conflict-free.
// MODE 0: A gathered (feat | nodes[ind] | gfeat);  MODE 1: A dense [E][KDIM].
// EPI  0: relu(x + bias);  EPI 1: sigmoid(x + bias).  Output: Yout[E][HOUT].
template<int KDIM, int MODE, int EPI, int HOUT>
__global__ void __launch_bounds__(256, 3) gemm_mma(
    const float* __restrict__ Af, const float* __restrict__ nodes,
    const float* __restrict__ gfeat, const int* __restrict__ ind,
    const float* __restrict__ W, const float* __restrict__ bias,
    float* __restrict__ Yout)
{
    constexpr int BM = 128, BN = 128, BK = 32;
    constexpr int PA = 36;    // A smem row stride (floats)
    constexpr int PB = 136;   // B smem row stride (floats)
    constexpr int STAGEF = BM * PA + BK * PB;        // 8960 floats / stage
    constexpr int NC = KDIM / BK;

    extern __shared__ float sm[];

    const int tid  = threadIdx.x;
    const int wid  = tid >> 5;
    const int lane = tid & 31;
    const int warpM = wid & 3;       // 0..3
    const int warpN = wid >> 2;      // 0..1
    const int eBase = blockIdx.x * BM;
    const int nBase = blockIdx.y * BN;

    const int grp = lane >> 2;       // 0..7
    const int tig = lane & 3;        // 0..3

    float acc[2][8][4];
    #pragma unroll
    for (int i = 0; i < 2; i++)
        #pragma unroll
        for (int j = 0; j < 8; j++)
            #pragma unroll
            for (int u = 0; u < 4; u++) acc[i][j][u] = 0.f;

    // ---- chunk loader ------------------------------------------------------
    const int arow  = tid >> 1;
    const int ahalf = (tid & 1) * 16;

    auto load_chunk = [&](int c) {
        float* As = sm + (c & 1) * STAGEF;
        float* Bs = As + BM * PA;
        const int k0 = c * BK;
        // ---- A
        const float* asrc;
        if (MODE == 0) {
            const int e = eBase + arow;
            const int k = k0 + ahalf;
            if (k < 256) {
                asrc = Af + (size_t)e * 256 + k;
            } else if (k < 1280) {
                const int j   = (k - 256) >> 8;
                const int nid = __ldg(ind + e * 4 + j);
                asrc = nodes + (size_t)nid * 256 + ((k - 256) & 255);
            } else {
                int lo = 0, hi = NGRAPH;
                while (hi - lo > 1) {
                    int mid = (lo + hi) >> 1;
                    if (g_gcum[mid] <= e) lo = mid; else hi = mid;
                }
                asrc = gfeat + (size_t)lo * 128 + (k - 1280);
            }
        } else {
            asrc = Af + (size_t)(eBase + arow) * KDIM + k0 + ahalf;
        }
        uint32_t adst = smem_u32(As + arow * PA + ahalf);
        #pragma unroll
        for (int q = 0; q < 4; q++)
            CP_ASYNC16(adst + q * 16, asrc + q * 4);
        // ---- B (row-major W [k][n])
        #pragma unroll
        for (int i = 0; i < 4; i++) {
            const int idx  = tid + 256 * i;
            const int krow = idx >> 5;
            const int col4 = idx & 31;
            const float* bsrc = W + (size_t)(k0 + krow) * HOUT + nBase + col4 * 4;
            uint32_t bdst = smem_u32(Bs + krow * PB + col4 * 4);
            CP_ASYNC16(bdst, bsrc);
        }
        CP_COMMIT();
    };

    load_chunk(0);

    for (int c = 0; c < NC; c++) {
        if (c + 1 < NC) {
            load_chunk(c + 1);
            CP_WAIT(1);
        } else {
            CP_WAIT(0);
        }
        __syncthreads();

        const uint32_t* As = (const uint32_t*)(sm + (c & 1) * STAGEF);
        const uint32_t* Bs = As + BM * PA;

        #pragma unroll
        for (int ks = 0; ks < 4; ks++) {
            const int kb = ks * 8;
            uint32_t a[2][4];
            #pragma unroll
            for (int mi = 0; mi < 2; mi++) {
                const int m = warpM * 32 + mi * 16 + grp;
                const int k = kb + tig;
                a[mi][0] = As[m * PA + k];
                a[mi][1] = As[(m + 8) * PA + k];
                a[mi][2] = As[m * PA + k + 4];
                a[mi][3] = As[(m + 8) * PA + k + 4];
            }
            #pragma unroll
            for (int ni = 0; ni < 8; ni++) {
                const int n = warpN * 64 + ni * 8 + grp;
                const uint32_t b0 = Bs[(kb + tig) * PB + n];
                const uint32_t b1 = Bs[(kb + tig + 4) * PB + n];
                mma_tf32(acc[0][ni], a[0], b0, b1);
                mma_tf32(acc[1][ni], a[1], b0, b1);
            }
        }
        __syncthreads();
    }

    // ---- epilogue: bias + activation -> Yout ------------------------------
    #pragma unroll
    for (int ni = 0; ni < 8; ni++) {
        const int col = nBase + warpN * 64 + ni * 8 + tig * 2;
        const float2 bb = *(const float2*)(bias + col);
        #pragma unroll
        for (int mi = 0; mi < 2; mi++) {
            const int e0 = eBase + warpM * 32 + mi * 16 + grp;
            #pragma unroll
            for (int h = 0; h < 2; h++) {       // rows e0, e0+8
                float x0 = acc[mi][ni][h * 2 + 0] + bb.x;
                float x1 = acc[mi][ni][h * 2 + 1] + bb.y;
                float2 v;
                if (EPI == 0) {
                    v.x = fmaxf(x0, 0.f);
                    v.y = fmaxf(x1, 0.f);
                } else {
                    v.x = 1.f / (1.f + __expf(-x0));
                    v.y = 1.f / (1.f + __expf(-x1));
                }
                *(float2*)(Yout + (size_t)(e0 + h * 8) * HOUT + col) = v;
            }
        }
    }
}

// ---------------- LayerNorm over last dim (256) ------------------------------
__global__ void __launch_bounds__(256) k_ln(
    const float* __restrict__ H, const float* __restrict__ gamma,
    const float* __restrict__ beta, float* __restrict__ out)
{
    const int row  = blockIdx.x * 8 + (threadIdx.x >> 5);
    const int lane = threadIdx.x & 31;
    const float* hp = H + (size_t)row * 256 + lane * 8;
    float4 v0 = *(const float4*)(hp);
    float4 v1 = *(const float4*)(hp + 4);
    float s  = v0.x + v0.y + v0.z + v0.w + v1.x + v1.y + v1.z + v1.w;
    float sq = v0.x*v0.x + v0.y*v0.y + v0.z*v0.z + v0.w*v0.w
             + v1.x*v1.x + v1.y*v1.y + v1.z*v1.z + v1.w*v1.w;
    #pragma unroll
    for (int o = 16; o > 0; o >>= 1) {
        s  += __shfl_xor_sync(0xFFFFFFFFu, s,  o);
        sq += __shfl_xor_sync(0xFFFFFFFFu, sq, o);
    }
    const float mu  = s * (1.f / 256.f);
    const float var = sq * (1.f / 256.f) - mu * mu;
    const float rs  = rsqrtf(var + 1e-3f);
    const float4 g0 = *(const float4*)(gamma + lane * 8);
    const float4 g1 = *(const float4*)(gamma + lane * 8 + 4);
    const float4 b0 = *(const float4*)(beta + lane * 8);
    const float4 b1 = *(const float4*)(beta + lane * 8 + 4);
    float4 o0, o1;
    o0.x = g0.x * (v0.x - mu) * rs + b0.x;
    o0.y = g0.y * (v0.y - mu) * rs + b0.y;
    o0.z = g0.z * (v0.z - mu) * rs + b0.z;
    o0.w = g0.w * (v0.w - mu) * rs + b0.w;
    o1.x = g1.x * (v1.x - mu) * rs + b1.x;
    o1.y = g1.y * (v1.y - mu) * rs + b1.y;
    o1.z = g1.z * (v1.z - mu) * rs + b1.z;
    o1.w = g1.w * (v1.w - mu) * rs + b1.w;
    float* op = out + (size_t)row * 256 + lane * 8;
    *(float4*)(op)     = o0;
    *(float4*)(op + 4) = o1;
}

// ---------------------------------------------------------------------------
extern "C" void kernel_launch(void* const* d_in, const int* in_sizes, int n_in,
                              void* d_out, int out_size)
{
    const float* feat  = (const float*)d_in[0];
    const float* nodes = (const float*)d_in[1];
    const float* gfeat = (const float*)d_in[2];
    const int*   ind   = (const int*)  d_in[3];
    const int*   num   = (const int*)  d_in[4];
    const float* W1    = (const float*)d_in[5];
    const float* b1    = (const float*)d_in[6];
    const float* W2    = (const float*)d_in[7];
    const float* b2    = (const float*)d_in[8];
    const float* W3    = (const float*)d_in[9];
    const float* b3    = (const float*)d_in[10];
    const float* gamma = (const float*)d_in[11];
    const float* beta  = (const float*)d_in[12];
    float* out = (float*)d_out;

    constexpr int PA = 36, PB = 136;
    const int SMEM_BYTES = 2 * (128 * PA + 32 * PB) * 4;   // 71680 -> 3 CTAs/SM

    cudaFuncSetAttribute(gemm_mma<D_IN, 0, 0, H1>,
                         cudaFuncAttributeMaxDynamicSharedMemorySize, SMEM_BYTES);
    cudaFuncSetAttribute(gemm_mma<H1, 1, 0, H2>,
                         cudaFuncAttributeMaxDynamicSharedMemorySize, SMEM_BYTES);
    cudaFuncSetAttribute(gemm_mma<H2, 1, 1, H3>,
                         cudaFuncAttributeMaxDynamicSharedMemorySize, SMEM_BYTES);

    float* Y1; cudaGetSymbolAddress((void**)&Y1, g_Y1);
    float* Y2; cudaGetSymbolAddress((void**)&Y2, g_Y2);

    k_prefix<<<1, 32>>>(num);

    gemm_mma<D_IN, 0, 0, H1><<<dim3(E_TOT / 128, H1 / 128), 256, SMEM_BYTES>>>(
        feat, nodes, gfeat, ind, W1, b1, Y1);

    gemm_mma<H1, 1, 0, H2><<<dim3(E_TOT / 128, H2 / 128), 256, SMEM_BYTES>>>(
        Y1, nullptr, nullptr, nullptr, W2, b2, Y2);

    gemm_mma<H2, 1, 1, H3><<<dim3(E_TOT / 128, H3 / 128), 256, SMEM_BYTES>>>(
        Y2, nullptr, nullptr, nullptr, W3, b3, Y1);

    k_ln<<<E_TOT / 8, 256>>>(Y1, gamma, beta, out);
}

// round 14
// speedup vs baseline: 1.2899x; 1.2899x over previous
#include <cuda_runtime.h>
#include <cstdint>
#include <math.h>

#define E_TOT 102400
#define NGRAPH 64
#define D_IN   1408
#define H1     512
#define H2     512
#define H3     256

// ---------------- scratch (__device__ globals; no allocs allowed) ----------
__device__ float g_Y1[(size_t)E_TOT * H1];   // also holds sigmoid output for LN
__device__ float g_Y2[(size_t)E_TOT * H2];
__device__ int   g_gcum[NGRAPH + 1];

// ---------------- helpers ---------------------------------------------------
#define CP_ASYNC16(dst, src) \
    asm volatile("cp.async.cg.shared.global [%0], [%1], 16;" :: "r"(dst), "l"(src) : "memory")
#define CP_COMMIT() asm volatile("cp.async.commit_group;" ::: "memory")
#define CP_WAIT(n)  asm volatile("cp.async.wait_group %0;" :: "n"(n) : "memory")

__device__ __forceinline__ uint32_t smem_u32(const void* p) {
    uint32_t a;
    asm("{ .reg .u64 t; cvta.to.shared.u64 t, %1; cvt.u32.u64 %0, t; }"
        : "=r"(a) : "l"(p));
    return a;
}

// m16n8k8 tf32 mma: D(16x8,f32) += A(16x8,tf32) * B(8x8,tf32)
__device__ __forceinline__ void mma_tf32(float* c, const uint32_t* a,
                                         uint32_t b0, uint32_t b1) {
    asm volatile(
        "mma.sync.aligned.m16n8k8.row.col.f32.tf32.tf32.f32 "
        "{%0,%1,%2,%3}, {%4,%5,%6,%7}, {%8,%9}, {%0,%1,%2,%3};"
        : "+f"(c[0]), "+f"(c[1]), "+f"(c[2]), "+f"(c[3])
        : "r"(a[0]), "r"(a[1]), "r"(a[2]), "r"(a[3]), "r"(b0), "r"(b1));
}

// ---------------- Kernel 0: prefix sum of num -------------------------------
__global__ void k_prefix(const int* __restrict__ num) {
    if (threadIdx.x == 0) {
        int s = 0;
        g_gcum[0] = 0;
        for (int i = 0; i < NGRAPH; i++) { s += num[i]; g_gcum[i + 1] = s; }
    }
}

// ---------------- tiled tf32 GEMM -------------------------------------------
// R10 base (3 cp.async stages, one sync/chunk) + REGISTER-LEVEL FRAGMENT
// DOUBLE BUFFERING: fragments for ks+1 are loaded while ks's MMAs issue,
// hiding the 29-cyc LDS latency behind tensor work.
// __launch_bounds__(256, 2) pins regs at 128 (2 CTAs x 256 thr x 128 = full RF).
// Tile: BM=128, BN=128, BK=32. 8 warps (4M x 2N), warp 32x64.
// MODE 0: A gathered (feat | nodes[ind] | gfeat);  MODE 1: A dense [E][KDIM].
// EPI  0: relu(x + bias);  EPI 1: sigmoid(x + bias).  Output: Yout[E][HOUT].
template<int KDIM, int MODE, int EPI, int HOUT>
__global__ void __launch_bounds__(256, 2) gemm_mma(
    const float* __restrict__ Af, const float* __restrict__ nodes,
    const float* __restrict__ gfeat, const int* __restrict__ ind,
    const float* __restrict__ W, const float* __restrict__ bias,
    float* __restrict__ Yout)
{
    constexpr int BM = 128, BN = 128, BK = 32;
    constexpr int PA = 36;    // A smem row stride (floats)
    constexpr int PB = 136;   // B smem row stride (floats)
    constexpr int STAGEF = BM * PA + BK * PB;        // 8960 floats / stage
    constexpr int NC = KDIM / BK;

    extern __shared__ float sm[];

    const int tid  = threadIdx.x;
    const int wid  = tid >> 5;
    const int lane = tid & 31;
    const int warpM = wid & 3;       // 0..3
    const int warpN = wid >> 2;      // 0..1
    const int eBase = blockIdx.x * BM;
    const int nBase = blockIdx.y * BN;

    const int grp = lane >> 2;       // 0..7
    const int tig = lane & 3;        // 0..3

    float acc[2][8][4];
    #pragma unroll
    for (int i = 0; i < 2; i++)
        #pragma unroll
        for (int j = 0; j < 8; j++)
            #pragma unroll
            for (int u = 0; u < 4; u++) acc[i][j][u] = 0.f;

    // ---- chunk loader ------------------------------------------------------
    const int arow  = tid >> 1;
    const int ahalf = (tid & 1) * 16;

    auto load_chunk = [&](int c) {
        float* As = sm + (c % 3) * STAGEF;
        float* Bs = As + BM * PA;
        const int k0 = c * BK;
        // ---- A
        const float* asrc;
        if (MODE == 0) {
            const int e = eBase + arow;
            const int k = k0 + ahalf;
            if (k < 256) {
                asrc = Af + (size_t)e * 256 + k;
            } else if (k < 1280) {
                const int j   = (k - 256) >> 8;
                const int nid = __ldg(ind + e * 4 + j);
                asrc = nodes + (size_t)nid * 256 + ((k - 256) & 255);
            } else {
                int lo = 0, hi = NGRAPH;
                while (hi - lo > 1) {
                    int mid = (lo + hi) >> 1;
                    if (g_gcum[mid] <= e) lo = mid; else hi = mid;
                }
                asrc = gfeat + (size_t)lo * 128 + (k - 1280);
            }
        } else {
            asrc = Af + (size_t)(eBase + arow) * KDIM + k0 + ahalf;
        }
        uint32_t adst = smem_u32(As + arow * PA + ahalf);
        #pragma unroll
        for (int q = 0; q < 4; q++)
            CP_ASYNC16(adst + q * 16, asrc + q * 4);
        // ---- B (row-major W [k][n])
        #pragma unroll
        for (int i = 0; i < 4; i++) {
            const int idx  = tid + 256 * i;
            const int krow = idx >> 5;
            const int col4 = idx & 31;
            const float* bsrc = W + (size_t)(k0 + krow) * HOUT + nBase + col4 * 4;
            uint32_t bdst = smem_u32(Bs + krow * PB + col4 * 4);
            CP_ASYNC16(bdst, bsrc);
        }
        CP_COMMIT();
    };

    // ---- prologue: 2 chunks in flight --------------------------------------
    load_chunk(0);
    if (NC > 1) load_chunk(1);

    // fragment double buffers
    uint32_t a[2][2][4];       // [buf][mi][frag]
    uint32_t b0r[2][8], b1r[2][8];

    for (int c = 0; c < NC; c++) {
        if (c + 1 < NC) CP_WAIT(1); else CP_WAIT(0);   // chunk c landed
        __syncthreads();                                // all warps past compute(c-1)
        if (c + 2 < NC) load_chunk(c + 2);              // stage (c-1)%3: safe after sync

        const uint32_t* As = (const uint32_t*)(sm + (c % 3) * STAGEF);
        const uint32_t* Bs = As + BM * PA;

        // load fragments for ks=0 into buffer 0
        {
            const int k = tig;
            #pragma unroll
            for (int mi = 0; mi < 2; mi++) {
                const int m = warpM * 32 + mi * 16 + grp;
                a[0][mi][0] = As[m * PA + k];
                a[0][mi][1] = As[(m + 8) * PA + k];
                a[0][mi][2] = As[m * PA + k + 4];
                a[0][mi][3] = As[(m + 8) * PA + k + 4];
            }
            #pragma unroll
            for (int ni = 0; ni < 8; ni++) {
                const int n = warpN * 64 + ni * 8 + grp;
                b0r[0][ni] = Bs[(k) * PB + n];
                b1r[0][ni] = Bs[(k + 4) * PB + n];
            }
        }

        #pragma unroll
        for (int ks = 0; ks < 4; ks++) {
            const int cur = ks & 1;
            const int nxt = cur ^ 1;
            if (ks < 3) {
                // prefetch ks+1 fragments (independent of cur MMAs)
                const int k = (ks + 1) * 8 + tig;
                #pragma unroll
                for (int mi = 0; mi < 2; mi++) {
                    const int m = warpM * 32 + mi * 16 + grp;
                    a[nxt][mi][0] = As[m * PA + k];
                    a[nxt][mi][1] = As[(m + 8) * PA + k];
                    a[nxt][mi][2] = As[m * PA + k + 4];
                    a[nxt][mi][3] = As[(m + 8) * PA + k + 4];
                }
                #pragma unroll
                for (int ni = 0; ni < 8; ni++) {
                    const int n = warpN * 64 + ni * 8 + grp;
                    b0r[nxt][ni] = Bs[(k) * PB + n];
                    b1r[nxt][ni] = Bs[(k + 4) * PB + n];
                }
            }
            #pragma unroll
            for (int ni = 0; ni < 8; ni++) {
                mma_tf32(acc[0][ni], a[cur][0], b0r[cur][ni], b1r[cur][ni]);
                mma_tf32(acc[1][ni], a[cur][1], b0r[cur][ni], b1r[cur][ni]);
            }
        }
    }

    // ---- epilogue: bias + activation -> Yout ------------------------------
    #pragma unroll
    for (int ni = 0; ni < 8; ni++) {
        const int col = nBase + warpN * 64 + ni * 8 + tig * 2;
        const float2 bb = *(const float2*)(bias + col);
        #pragma unroll
        for (int mi = 0; mi < 2; mi++) {
            const int e0 = eBase + warpM * 32 + mi * 16 + grp;
            #pragma unroll
            for (int h = 0; h < 2; h++) {       // rows e0, e0+8
                float x0 = acc[mi][ni][h * 2 + 0] + bb.x;
                float x1 = acc[mi][ni][h * 2 + 1] + bb.y;
                float2 v;
                if (EPI == 0) {
                    v.x = fmaxf(x0, 0.f);
                    v.y = fmaxf(x1, 0.f);
                } else {
                    v.x = 1.f / (1.f + __expf(-x0));
                    v.y = 1.f / (1.f + __expf(-x1));
                }
                *(float2*)(Yout + (size_t)(e0 + h * 8) * HOUT + col) = v;
            }
        }
    }
}

// ---------------- LayerNorm over last dim (256) ------------------------------
__global__ void __launch_bounds__(256) k_ln(
    const float* __restrict__ H, const float* __restrict__ gamma,
    const float* __restrict__ beta, float* __restrict__ out)
{
    const int row  = blockIdx.x * 8 + (threadIdx.x >> 5);
    const int lane = threadIdx.x & 31;
    const float* hp = H + (size_t)row * 256 + lane * 8;
    float4 v0 = *(const float4*)(hp);
    float4 v1 = *(const float4*)(hp + 4);
    float s  = v0.x + v0.y + v0.z + v0.w + v1.x + v1.y + v1.z + v1.w;
    float sq = v0.x*v0.x + v0.y*v0.y + v0.z*v0.z + v0.w*v0.w
             + v1.x*v1.x + v1.y*v1.y + v1.z*v1.z + v1.w*v1.w;
    #pragma unroll
    for (int o = 16; o > 0; o >>= 1) {
        s  += __shfl_xor_sync(0xFFFFFFFFu, s,  o);
        sq += __shfl_xor_sync(0xFFFFFFFFu, sq, o);
    }
    const float mu  = s * (1.f / 256.f);
    const float var = sq * (1.f / 256.f) - mu * mu;
    const float rs  = rsqrtf(var + 1e-3f);
    const float4 g0 = *(const float4*)(gamma + lane * 8);
    const float4 g1 = *(const float4*)(gamma + lane * 8 + 4);
    const float4 b0 = *(const float4*)(beta + lane * 8);
    const float4 b1 = *(const float4*)(beta + lane * 8 + 4);
    float4 o0, o1;
    o0.x = g0.x * (v0.x - mu) * rs + b0.x;
    o0.y = g0.y * (v0.y - mu) * rs + b0.y;
    o0.z = g0.z * (v0.z - mu) * rs + b0.z;
    o0.w = g0.w * (v0.w - mu) * rs + b0.w;
    o1.x = g1.x * (v1.x - mu) * rs + b1.x;
    o1.y = g1.y * (v1.y - mu) * rs + b1.y;
    o1.z = g1.z * (v1.z - mu) * rs + b1.z;
    o1.w = g1.w * (v1.w - mu) * rs + b1.w;
    float* op = out + (size_t)row * 256 + lane * 8;
    *(float4*)(op)     = o0;
    *(float4*)(op + 4) = o1;
}

// ---------------------------------------------------------------------------
extern "C" void kernel_launch(void* const* d_in, const int* in_sizes, int n_in,
                              void* d_out, int out_size)
{
    const float* feat  = (const float*)d_in[0];
    const float* nodes = (const float*)d_in[1];
    const float* gfeat = (const float*)d_in[2];
    const int*   ind   = (const int*)  d_in[3];
    const int*   num   = (const int*)  d_in[4];
    const float* W1    = (const float*)d_in[5];
    const float* b1    = (const float*)d_in[6];
    const float* W2    = (const float*)d_in[7];
    const float* b2    = (const float*)d_in[8];
    const float* W3    = (const float*)d_in[9];
    const float* b3    = (const float*)d_in[10];
    const float* gamma = (const float*)d_in[11];
    const float* beta  = (const float*)d_in[12];
    float* out = (float*)d_out;

    constexpr int PA = 36, PB = 136;
    const int SMEM_BYTES = 3 * (128 * PA + 32 * PB) * 4;   // 107520 -> 2 CTAs/SM

    cudaFuncSetAttribute(gemm_mma<D_IN, 0, 0, H1>,
                         cudaFuncAttributeMaxDynamicSharedMemorySize, SMEM_BYTES);
    cudaFuncSetAttribute(gemm_mma<H1, 1, 0, H2>,
                         cudaFuncAttributeMaxDynamicSharedMemorySize, SMEM_BYTES);
    cudaFuncSetAttribute(gemm_mma<H2, 1, 1, H3>,
                         cudaFuncAttributeMaxDynamicSharedMemorySize, SMEM_BYTES);

    float* Y1; cudaGetSymbolAddress((void**)&Y1, g_Y1);
    float* Y2; cudaGetSymbolAddress((void**)&Y2, g_Y2);

    k_prefix<<<1, 32>>>(num);

    gemm_mma<D_IN, 0, 0, H1><<<dim3(E_TOT / 128, H1 / 128), 256, SMEM_BYTES>>>(
        feat, nodes, gfeat, ind, W1, b1, Y1);

    gemm_mma<H1, 1, 0, H2><<<dim3(E_TOT / 128, H2 / 128), 256, SMEM_BYTES>>>(
        Y1, nullptr, nullptr, nullptr, W2, b2, Y2);

    gemm_mma<H2, 1, 1, H3><<<dim3(E_TOT / 128, H3 / 128), 256, SMEM_BYTES>>>(
        Y2, nullptr, nullptr, nullptr, W3, b3, Y1);

    k_ln<<<E_TOT / 8, 256>>>(Y1, gamma, beta, out);
}

// round 15
// speedup vs baseline: 2.1714x; 1.6833x over previous
#include <cuda_runtime.h>
#include <cuda_fp16.h>
#include <cstdint>
#include <math.h>

#define E_TOT 102400
#define N_TOT 100000
#define NGRAPH 64
#define D_IN   1408
#define H1     512
#define H2     512
#define H3     256

// ---------------- scratch (__device__ globals; no allocs allowed) ----------
__device__ __half   g_hfeat[(size_t)E_TOT * 256];
__device__ __half   g_hnodes[(size_t)N_TOT * 256];
__device__ __half   g_hgfeat[(size_t)NGRAPH * 128];
__device__ uint32_t g_W1p[(size_t)(D_IN / 2) * H1];   // half2(k,k+1) packed
__device__ uint32_t g_W2p[(size_t)(H1 / 2) * H2];
__device__ uint32_t g_W3p[(size_t)(H2 / 2) * H3];
__device__ __half   g_hY1[(size_t)E_TOT * H1];
__device__ __half   g_hY2[(size_t)E_TOT * H2];
__device__ float    g_Hf[(size_t)E_TOT * H3];         // sigmoid out (fp32) for LN
__device__ int      g_gcum[NGRAPH + 1];

// ---------------- helpers ---------------------------------------------------
#define CP_ASYNC16(dst, src) \
    asm volatile("cp.async.cg.shared.global [%0], [%1], 16;" :: "r"(dst), "l"(src) : "memory")
#define CP_COMMIT() asm volatile("cp.async.commit_group;" ::: "memory")
#define CP_WAIT(n)  asm volatile("cp.async.wait_group %0;" :: "n"(n) : "memory")

__device__ __forceinline__ uint32_t smem_u32(const void* p) {
    uint32_t a;
    asm("{ .reg .u64 t; cvta.to.shared.u64 t, %1; cvt.u32.u64 %0, t; }"
        : "=r"(a) : "l"(p));
    return a;
}

// m16n8k16 fp16 mma, fp32 accumulate
__device__ __forceinline__ void mma_f16(float* c, const uint32_t* a,
                                        uint32_t b0, uint32_t b1) {
    asm volatile(
        "mma.sync.aligned.m16n8k16.row.col.f32.f16.f16.f32 "
        "{%0,%1,%2,%3}, {%4,%5,%6,%7}, {%8,%9}, {%0,%1,%2,%3};"
        : "+f"(c[0]), "+f"(c[1]), "+f"(c[2]), "+f"(c[3])
        : "r"(a[0]), "r"(a[1]), "r"(a[2]), "r"(a[3]), "r"(b0), "r"(b1));
}

// ---------------- pre-pass kernels ------------------------------------------
__global__ void k_prefix(const int* __restrict__ num) {
    if (threadIdx.x == 0) {
        int s = 0;
        g_gcum[0] = 0;
        for (int i = 0; i < NGRAPH; i++) { s += num[i]; g_gcum[i + 1] = s; }
    }
}

// fp32 -> fp16, vectorized (n4 = count/4)
__global__ void __launch_bounds__(256) k_cvt(
    const float4* __restrict__ src, uint2* __restrict__ dst, int n4)
{
    int i = blockIdx.x * 256 + threadIdx.x;
    if (i < n4) {
        float4 v = src[i];
        __half2 lo = __floats2half2_rn(v.x, v.y);
        __half2 hi = __floats2half2_rn(v.z, v.w);
        uint2 o;
        o.x = *(uint32_t*)&lo;
        o.y = *(uint32_t*)&hi;
        dst[i] = o;
    }
}

// W[k][n] fp32 -> Wp[k2][n] = half2(W[2k2][n], W[2k2+1][n])
__global__ void __launch_bounds__(256) k_packW(
    const float* __restrict__ W, uint32_t* __restrict__ Wp, int K2, int N)
{
    int i = blockIdx.x * 256 + threadIdx.x;
    if (i < K2 * N) {
        int k2 = i / N, n = i - k2 * N;
        __half2 v = __floats2half2_rn(W[(size_t)(2 * k2) * N + n],
                                      W[(size_t)(2 * k2 + 1) * N + n]);
        Wp[i] = *(uint32_t*)&v;
    }
}

// ---------------- fp16 tensor-core GEMM -------------------------------------
// BM=128, BN=128, BK=32 (16 k2). 8 warps (4M x 2N), warp tile 32x64.
// A smem: 128 rows x 20 u32 (16 data half2 + pad)  — banks 20g+t: conflict-free
// B smem: 16 k2-rows x 136 u32 (128 data + pad)    — banks 8t+8n+g: conflict-free
// 3 cp.async stages (18,944 B each), one __syncthreads per chunk,
// fragment double-buffer across the 2 k16-steps.
// MODE 0: A gathered fp16 (hfeat|hnodes[ind]|hgfeat); MODE 1: A = dense fp16.
// EPI 0: relu -> fp16 Yh;  EPI 1: sigmoid -> fp32 Yf.
template<int KDIM, int MODE, int EPI, int HOUT>
__global__ void __launch_bounds__(256, 2) gemm_hmma(
    const __half* __restrict__ Af, const __half* __restrict__ nodes,
    const __half* __restrict__ gfeat, const int* __restrict__ ind,
    const uint32_t* __restrict__ Wp, const float* __restrict__ bias,
    __half* __restrict__ Yh, float* __restrict__ Yf)
{
    constexpr int PAH = 20, PBN = 136;
    constexpr int STAGEU = 128 * PAH + 16 * PBN;     // 4736 u32 / stage
    constexpr int NC = KDIM / 32;

    extern __shared__ uint32_t smU[];

    const int tid  = threadIdx.x;
    const int wid  = tid >> 5;
    const int lane = tid & 31;
    const int warpM = wid & 3;
    const int warpN = wid >> 2;
    const int eBase = blockIdx.x * 128;
    const int nBase = blockIdx.y * 128;

    const int grp = lane >> 2;       // 0..7
    const int tig = lane & 3;        // 0..3

    float acc[2][8][4];
    #pragma unroll
    for (int i = 0; i < 2; i++)
        #pragma unroll
        for (int j = 0; j < 8; j++)
            #pragma unroll
            for (int u = 0; u < 4; u++) acc[i][j][u] = 0.f;

    // ---- chunk loader ------------------------------------------------------
    const int arow  = tid >> 1;
    const int apart = tid & 1;       // 32B half of the 64B row chunk

    auto load_chunk = [&](int c) {
        uint32_t* As = smU + (c % 3) * STAGEU;
        uint32_t* Bs = As + 128 * PAH;
        const int k0 = c * 32;
        // ---- A (fp16 rows; 32 k = 64B per row)
        const __half* asrc;
        if (MODE == 0) {
            const int e = eBase + arow;
            if (k0 < 256) {
                asrc = Af + (size_t)e * 256 + k0;
            } else if (k0 < 1280) {
                const int j   = (k0 - 256) >> 8;
                const int nid = __ldg(ind + e * 4 + j);
                asrc = nodes + (size_t)nid * 256 + ((k0 - 256) & 255);
            } else {
                int lo = 0, hi = NGRAPH;
                while (hi - lo > 1) {
                    int mid = (lo + hi) >> 1;
                    if (g_gcum[mid] <= e) lo = mid; else hi = mid;
                }
                asrc = gfeat + (size_t)lo * 128 + (k0 - 1280);
            }
        } else {
            asrc = Af + (size_t)(eBase + arow) * KDIM + k0;
        }
        asrc += apart * 16;
        uint32_t adst = smem_u32(As + arow * PAH + apart * 8);
        CP_ASYNC16(adst,      asrc);
        CP_ASYNC16(adst + 16, asrc + 8);
        // ---- B (Wp rows k2 = c*16 .. +15, 128 u32 wide)
        #pragma unroll
        for (int i = 0; i < 2; i++) {
            const int c16 = tid * 2 + i;          // 0..511 16B-chunks
            const int row = c16 >> 5;             // 0..15
            const int col = (c16 & 31) * 4;       // u32 col
            const uint32_t* bsrc = Wp + (size_t)(c * 16 + row) * HOUT + nBase + col;
            CP_ASYNC16(smem_u32(Bs + row * PBN + col), bsrc);
        }
        CP_COMMIT();
    };

    // ---- prologue: 2 chunks in flight --------------------------------------
    load_chunk(0);
    if (NC > 1) load_chunk(1);

    uint32_t a[2][2][4];        // [buf][mi][frag]
    uint32_t b[2][8][2];        // [buf][ni][b0/b1]

    for (int c = 0; c < NC; c++) {
        if (c + 1 < NC) CP_WAIT(1); else CP_WAIT(0);
        __syncthreads();
        if (c + 2 < NC) load_chunk(c + 2);

        const uint32_t* As = smU + (c % 3) * STAGEU;
        const uint32_t* Bs = As + 128 * PAH;

        // fragments for both k16-steps (lf0 latency covered by lf1 issue)
        #pragma unroll
        for (int ks = 0; ks < 2; ks++) {
            const int k2 = ks * 8 + tig;
            #pragma unroll
            for (int mi = 0; mi < 2; mi++) {
                const int m = warpM * 32 + mi * 16 + grp;
                a[ks][mi][0] = As[m * PAH + k2];
                a[ks][mi][1] = As[(m + 8) * PAH + k2];
                a[ks][mi][2] = As[m * PAH + k2 + 4];
                a[ks][mi][3] = As[(m + 8) * PAH + k2 + 4];
            }
            #pragma unroll
            for (int ni = 0; ni < 8; ni++) {
                const int n = warpN * 64 + ni * 8 + grp;
                b[ks][ni][0] = Bs[k2 * PBN + n];
                b[ks][ni][1] = Bs[(k2 + 4) * PBN + n];
            }
        }
        #pragma unroll
        for (int ks = 0; ks < 2; ks++)
            #pragma unroll
            for (int ni = 0; ni < 8; ni++) {
                mma_f16(acc[0][ni], a[ks][0], b[ks][ni][0], b[ks][ni][1]);
                mma_f16(acc[1][ni], a[ks][1], b[ks][ni][0], b[ks][ni][1]);
            }
    }

    // ---- epilogue ----------------------------------------------------------
    #pragma unroll
    for (int ni = 0; ni < 8; ni++) {
        const int col = nBase + warpN * 64 + ni * 8 + tig * 2;
        const float2 bb = *(const float2*)(bias + col);
        #pragma unroll
        for (int mi = 0; mi < 2; mi++) {
            const int e0 = eBase + warpM * 32 + mi * 16 + grp;
            #pragma unroll
            for (int h = 0; h < 2; h++) {
                float x0 = acc[mi][ni][h * 2 + 0] + bb.x;
                float x1 = acc[mi][ni][h * 2 + 1] + bb.y;
                const size_t off = (size_t)(e0 + h * 8) * HOUT + col;
                if (EPI == 0) {
                    __half2 v = __floats2half2_rn(fmaxf(x0, 0.f), fmaxf(x1, 0.f));
                    *(uint32_t*)(Yh + off) = *(uint32_t*)&v;
                } else {
                    float2 v;
                    v.x = 1.f / (1.f + __expf(-x0));
                    v.y = 1.f / (1.f + __expf(-x1));
                    *(float2*)(Yf + off) = v;
                }
            }
        }
    }
}

// ---------------- LayerNorm over last dim (256) ------------------------------
__global__ void __launch_bounds__(256) k_ln(
    const float* __restrict__ H, const float* __restrict__ gamma,
    const float* __restrict__ beta, float* __restrict__ out)
{
    const int row  = blockIdx.x * 8 + (threadIdx.x >> 5);
    const int lane = threadIdx.x & 31;
    const float* hp = H + (size_t)row * 256 + lane * 8;
    float4 v0 = *(const float4*)(hp);
    float4 v1 = *(const float4*)(hp + 4);
    float s  = v0.x + v0.y + v0.z + v0.w + v1.x + v1.y + v1.z + v1.w;
    float sq = v0.x*v0.x + v0.y*v0.y + v0.z*v0.z + v0.w*v0.w
             + v1.x*v1.x + v1.y*v1.y + v1.z*v1.z + v1.w*v1.w;
    #pragma unroll
    for (int o = 16; o > 0; o >>= 1) {
        s  += __shfl_xor_sync(0xFFFFFFFFu, s,  o);
        sq += __shfl_xor_sync(0xFFFFFFFFu, sq, o);
    }
    const float mu  = s * (1.f / 256.f);
    const float var = sq * (1.f / 256.f) - mu * mu;
    const float rs  = rsqrtf(var + 1e-3f);
    const float4 g0 = *(const float4*)(gamma + lane * 8);
    const float4 g1 = *(const float4*)(gamma + lane * 8 + 4);
    const float4 b0 = *(const float4*)(beta + lane * 8);
    const float4 b1 = *(const float4*)(beta + lane * 8 + 4);
    float4 o0, o1;
    o0.x = g0.x * (v0.x - mu) * rs + b0.x;
    o0.y = g0.y * (v0.y - mu) * rs + b0.y;
    o0.z = g0.z * (v0.z - mu) * rs + b0.z;
    o0.w = g0.w * (v0.w - mu) * rs + b0.w;
    o1.x = g1.x * (v1.x - mu) * rs + b1.x;
    o1.y = g1.y * (v1.y - mu) * rs + b1.y;
    o1.z = g1.z * (v1.z - mu) * rs + b1.z;
    o1.w = g1.w * (v1.w - mu) * rs + b1.w;
    float* op = out + (size_t)row * 256 + lane * 8;
    *(float4*)(op)     = o0;
    *(float4*)(op + 4) = o1;
}

// ---------------------------------------------------------------------------
extern "C" void kernel_launch(void* const* d_in, const int* in_sizes, int n_in,
                              void* d_out, int out_size)
{
    const float* feat  = (const float*)d_in[0];
    const float* nodes = (const float*)d_in[1];
    const float* gfeat = (const float*)d_in[2];
    const int*   ind   = (const int*)  d_in[3];
    const int*   num   = (const int*)  d_in[4];
    const float* W1    = (const float*)d_in[5];
    const float* b1    = (const float*)d_in[6];
    const float* W2    = (const float*)d_in[7];
    const float* b2    = (const float*)d_in[8];
    const float* W3    = (const float*)d_in[9];
    const float* b3    = (const float*)d_in[10];
    const float* gamma = (const float*)d_in[11];
    const float* beta  = (const float*)d_in[12];
    float* out = (float*)d_out;

    const int SMEM_BYTES = 3 * (128 * 20 + 16 * 136) * 4;   // 56832

    cudaFuncSetAttribute(gemm_hmma<D_IN, 0, 0, H1>,
                         cudaFuncAttributeMaxDynamicSharedMemorySize, SMEM_BYTES);
    cudaFuncSetAttribute(gemm_hmma<H1, 1, 0, H2>,
                         cudaFuncAttributeMaxDynamicSharedMemorySize, SMEM_BYTES);
    cudaFuncSetAttribute(gemm_hmma<H2, 1, 1, H3>,
                         cudaFuncAttributeMaxDynamicSharedMemorySize, SMEM_BYTES);

    __half *hfeat, *hnodes, *hgfeat, *hY1, *hY2;
    uint32_t *W1p, *W2p, *W3p;
    float *Hf;
    cudaGetSymbolAddress((void**)&hfeat,  g_hfeat);
    cudaGetSymbolAddress((void**)&hnodes, g_hnodes);
    cudaGetSymbolAddress((void**)&hgfeat, g_hgfeat);
    cudaGetSymbolAddress((void**)&W1p,    g_W1p);
    cudaGetSymbolAddress((void**)&W2p,    g_W2p);
    cudaGetSymbolAddress((void**)&W3p,    g_W3p);
    cudaGetSymbolAddress((void**)&hY1,    g_hY1);
    cudaGetSymbolAddress((void**)&hY2,    g_hY2);
    cudaGetSymbolAddress((void**)&Hf,     g_Hf);

    k_prefix<<<1, 32>>>(num);

    // fp32 -> fp16 conversions
    {
        int n4 = E_TOT * 256 / 4;
        k_cvt<<<(n4 + 255) / 256, 256>>>((const float4*)feat, (uint2*)hfeat, n4);
        n4 = N_TOT * 256 / 4;
        k_cvt<<<(n4 + 255) / 256, 256>>>((const float4*)nodes, (uint2*)hnodes, n4);
        n4 = NGRAPH * 128 / 4;
        k_cvt<<<(n4 + 255) / 256, 256>>>((const float4*)gfeat, (uint2*)hgfeat, n4);
    }
    // weight packing
    k_packW<<<((D_IN / 2) * H1 + 255) / 256, 256>>>(W1, W1p, D_IN / 2, H1);
    k_packW<<<((H1 / 2) * H2 + 255) / 256, 256>>>(W2, W2p, H1 / 2, H2);
    k_packW<<<((H2 / 2) * H3 + 255) / 256, 256>>>(W3, W3p, H2 / 2, H3);

    gemm_hmma<D_IN, 0, 0, H1><<<dim3(E_TOT / 128, H1 / 128), 256, SMEM_BYTES>>>(
        hfeat, hnodes, hgfeat, ind, W1p, b1, hY1, nullptr);

    gemm_hmma<H1, 1, 0, H2><<<dim3(E_TOT / 128, H2 / 128), 256, SMEM_BYTES>>>(
        hY1, nullptr, nullptr, nullptr, W2p, b2, hY2, nullptr);

    gemm_hmma<H2, 1, 1, H3><<<dim3(E_TOT / 128, H3 / 128), 256, SMEM_BYTES>>>(
        hY2, nullptr, nullptr, nullptr, W3p, b3, nullptr, Hf);

    k_ln<<<E_TOT / 8, 256>>>(Hf, gamma, beta, out);
}